// round 16
// baseline (speedup 1.0000x reference)
#include <cuda_runtime.h>
#include <cuda_bf16.h>
#include <cstdint>

namespace {
constexpr int H=448, Wd=608, K=32, Bn=2, TPB=512, PXT=128;
constexpr int NSM=148;
constexpr int NTILES=H*Bn*5;                // 4480
constexpr int XS=72;                        // bf16 row stride (144B)
constexpr int XSPL=128*XS*2;                // 18432 per activation split
constexpr int WSPL=64*XS*2;                 // 9216
constexpr int W3SPL=32*XS*2;                // 4608
constexpr float TAU=2e-4f;

constexpr int SM_B1=0, SM_B2=256, SM_B3=512, SM_BR=640;
constexpr int SM_PV1=1024;                  // [4][128] f32
constexpr int SM_PV2=3072;
constexpr int SM_PI1=5120;
constexpr int SM_NF=7168;
constexpr int SM_FL=7296;                   // [128] int
constexpr int SM_SCR=7808;                  // 4 warps x 128 f32 (2048)
constexpr int SM_XA=9856;                   // raw x prefetch [64][128] f32 (32768)
constexpr int SM_X =42624;                  // X splits buf0 (36864)
constexpr int SM_X2=79488;                  // X splits buf1 (36864)
constexpr int SM_Y0=116352;                 // Y0 splits (36864); Dr f32 overlay
constexpr int SM_W1=153216;
constexpr int SM_W2=171648;
constexpr int SM_W3=190080;
constexpr int SM_WR=199296;
constexpr int SMEM_BYTES=217728;
constexpr int SM_DR=SM_Y0;
constexpr int DRS=66;
}

__device__ __forceinline__ float lrelu(float v){ return v>=0.f ? v : 0.01f*v; }
__device__ __forceinline__ uint32_t smem_u32(const void* p){
    uint32_t a;
    asm("{ .reg .u64 t; cvta.to.shared.u64 t, %1; cvt.u32.u64 %0, t; }" : "=r"(a) : "l"(p));
    return a;
}
__device__ __forceinline__ void sts32(uint32_t a, uint32_t v){
    asm volatile("st.shared.b32 [%0], %1;" :: "r"(a), "r"(v) : "memory");
}
__device__ __forceinline__ uint32_t lds32(uint32_t a){
    uint32_t v; asm volatile("ld.shared.b32 %0, [%1];" : "=r"(v) : "r"(a)); return v;
}
__device__ __forceinline__ void cp16(uint32_t dst, const void* src){
    asm volatile("cp.async.cg.shared.global [%0], [%1], 16;" :: "r"(dst), "l"(src) : "memory");
}
__device__ __forceinline__ void ldsm4(uint32_t addr, uint32_t* r){
    asm volatile("ldmatrix.sync.aligned.m8n8.x4.shared.b16 {%0,%1,%2,%3}, [%4];"
                 : "=r"(r[0]), "=r"(r[1]), "=r"(r[2]), "=r"(r[3]) : "r"(addr));
}
__device__ __forceinline__ void ldsm2(uint32_t addr, uint32_t* r){
    asm volatile("ldmatrix.sync.aligned.m8n8.x2.shared.b16 {%0,%1}, [%2];"
                 : "=r"(r[0]), "=r"(r[1]) : "r"(addr));
}
__device__ __forceinline__ void mma_bf16(float d[4], const uint32_t a[4], uint32_t b0, uint32_t b1){
    asm volatile("mma.sync.aligned.m16n8k16.row.col.f32.bf16.bf16.f32 "
                 "{%0,%1,%2,%3},{%4,%5,%6,%7},{%8,%9},{%0,%1,%2,%3};"
                 : "+f"(d[0]), "+f"(d[1]), "+f"(d[2]), "+f"(d[3])
                 : "r"(a[0]), "r"(a[1]), "r"(a[2]), "r"(a[3]), "r"(b0), "r"(b1));
}
__device__ __forceinline__ uint32_t prmt_(uint32_t a, uint32_t b, uint32_t s){
    uint32_t d; asm("prmt.b32 %0,%1,%2,%3;" : "=r"(d) : "r"(a), "r"(b), "r"(s)); return d;
}
__device__ __forceinline__ void split2pair(float a, float b, uint32_t s[2]){
    const uint32_t ia=__float_as_uint(a)+0x8000u, ib=__float_as_uint(b)+0x8000u;
    s[0]=prmt_(ia, ib, 0x7632u);                       // low16 = elem a(c), high16 = elem b(c+1)
    const float ra=a-__uint_as_float(ia&0xFFFF0000u);
    const float rb=b-__uint_as_float(ib&0xFFFF0000u);
    uint32_t r; asm("cvt.rn.bf16x2.f32 %0, %1, %2;" : "=r"(r) : "f"(rb), "f"(ra));
    s[1]=r;
}
// reconstruct 2 fp32 weights (cols c,c+1) from split pair words
__device__ __forceinline__ float2 recon2(uint32_t hi, uint32_t lo){
    const float2 h=__bfloat1622float2(*reinterpret_cast<__nv_bfloat162*>(&hi));
    const float2 l=__bfloat1622float2(*reinterpret_cast<__nv_bfloat162*>(&lo));
    return make_float2(h.x+l.x, h.y+l.y);
}

// ---- 2-split 3-pass emulated GEMMs; warp tile 32px x 16n ----
__device__ __forceinline__ void gemm3(uint32_t aB, uint32_t bB, float D[4][4]){
    uint32_t bf[4][2][4];
    #pragma unroll
    for(int ks=0;ks<4;++ks)
        #pragma unroll
        for(int s=0;s<2;++s) ldsm4(bB+s*WSPL+ks*32, bf[ks][s]);
    #pragma unroll
    for(int i=0;i<4;++i){ D[i][0]=D[i][1]=D[i][2]=D[i][3]=0.f; }
    constexpr int PA[3]={0,0,1}, PB[3]={0,1,0};
    #pragma unroll
    for(int ks=0;ks<4;++ks){
        uint32_t a[2][2][4];
        #pragma unroll
        for(int s=0;s<2;++s){
            ldsm4(aB+s*XSPL+ks*32, a[s][0]);
            ldsm4(aB+s*XSPL+16*XS*2+ks*32, a[s][1]);
        }
        #pragma unroll
        for(int p=0;p<3;++p)
            #pragma unroll
            for(int mt=0;mt<2;++mt)
                #pragma unroll
                for(int nt=0;nt<2;++nt)
                    mma_bf16(D[mt*2+nt], a[PA[p]][mt],
                             bf[ks][PB[p]][nt*2], bf[ks][PB[p]][nt*2+1]);
    }
}
__device__ __forceinline__ void gemm3_dual(uint32_t aB, uint32_t b1B, uint32_t b2B,
                                           float D1[4][4], float D2[4][4]){
    #pragma unroll
    for(int i=0;i<4;++i){ D1[i][0]=D1[i][1]=D1[i][2]=D1[i][3]=0.f;
                          D2[i][0]=D2[i][1]=D2[i][2]=D2[i][3]=0.f; }
    constexpr int PA[3]={0,0,1}, PB[3]={0,1,0};
    #pragma unroll
    for(int ks=0;ks<4;++ks){
        uint32_t a[2][2][4];
        #pragma unroll
        for(int s=0;s<2;++s){
            ldsm4(aB+s*XSPL+ks*32, a[s][0]);
            ldsm4(aB+s*XSPL+16*XS*2+ks*32, a[s][1]);
        }
        uint32_t bf1[2][4], bf2[2][4];
        #pragma unroll
        for(int s=0;s<2;++s){
            ldsm4(b1B+s*WSPL+ks*32, bf1[s]);
            ldsm4(b2B+s*WSPL+ks*32, bf2[s]);
        }
        #pragma unroll
        for(int p=0;p<3;++p)
            #pragma unroll
            for(int mt=0;mt<2;++mt)
                #pragma unroll
                for(int nt=0;nt<2;++nt){
                    mma_bf16(D1[mt*2+nt], a[PA[p]][mt], bf1[PB[p]][nt*2], bf1[PB[p]][nt*2+1]);
                    mma_bf16(D2[mt*2+nt], a[PA[p]][mt], bf2[PB[p]][nt*2], bf2[PB[p]][nt*2+1]);
                }
    }
}
__device__ __forceinline__ void gemm3_n8(uint32_t aB, uint32_t bB, float D[2][4]){
    uint32_t bf[4][2][2];
    #pragma unroll
    for(int ks=0;ks<4;++ks)
        #pragma unroll
        for(int s=0;s<2;++s) ldsm2(bB+s*W3SPL+ks*32, bf[ks][s]);
    #pragma unroll
    for(int i=0;i<2;++i){ D[i][0]=D[i][1]=D[i][2]=D[i][3]=0.f; }
    constexpr int PA[3]={0,0,1}, PB[3]={0,1,0};
    #pragma unroll
    for(int ks=0;ks<4;++ks){
        uint32_t a[2][2][4];
        #pragma unroll
        for(int s=0;s<2;++s){
            ldsm4(aB+s*XSPL+ks*32, a[s][0]);
            ldsm4(aB+s*XSPL+16*XS*2+ks*32, a[s][1]);
        }
        #pragma unroll
        for(int p=0;p<3;++p)
            #pragma unroll
            for(int mt=0;mt<2;++mt)
                mma_bf16(D[mt], a[PA[p]][mt], bf[ks][PB[p]][0], bf[ks][PB[p]][1]);
    }
}

__device__ __forceinline__ void epi2(float D[4][4], const float* __restrict__ bias,
                                     uint32_t outB, int wm, int wn, int lane){
    const int g=lane>>2, c2=2*(lane&3);
    #pragma unroll
    for(int mt=0;mt<2;++mt)
        #pragma unroll
        for(int nt=0;nt<2;++nt){
            const int n0=wn*16+nt*8+c2;
            const float bv0=bias[n0], bv1=bias[n0+1];
            const float* d=D[mt*2+nt];
            uint32_t s[2];
            const uint32_t a0=outB+((wm*32+mt*16+g)*XS+n0)*2;
            split2pair(lrelu(d[0]+bv0), lrelu(d[1]+bv1), s);
            sts32(a0,s[0]); sts32(a0+XSPL,s[1]);
            const uint32_t a1=a0+8*XS*2;
            split2pair(lrelu(d[2]+bv0), lrelu(d[3]+bv1), s);
            sts32(a1,s[0]); sts32(a1+XSPL,s[1]);
        }
}

__global__ void __launch_bounds__(TPB,1)
reg1stage_emu(const float* __restrict__ x,
              const float* __restrict__ W1g, const float* __restrict__ b1g,
              const float* __restrict__ W2g, const float* __restrict__ b2g,
              const float* __restrict__ W3g, const float* __restrict__ b3g,
              const float* __restrict__ Wr,  const float* __restrict__ br,
              float* __restrict__ out)
{
    extern __shared__ char smem[];
    const uint32_t sb = smem_u32(smem);
    float* smf = reinterpret_cast<float*>(smem);
    float* sV1 = reinterpret_cast<float*>(smem+SM_PV1);
    float* sV2 = reinterpret_cast<float*>(smem+SM_PV2);
    int*   sI1 = reinterpret_cast<int*>(smem+SM_PI1);
    int*   sNF = reinterpret_cast<int*>(smem+SM_NF);
    int*   sFL = reinterpret_cast<int*>(smem+SM_FL);
    float* scr = reinterpret_cast<float*>(smem+SM_SCR);
    float* xa  = reinterpret_cast<float*>(smem+SM_XA);
    const int tid=threadIdx.x, lane=tid&31, warp=tid>>5;
    const int wm=warp>>2, wn=warp&3;

    const size_t HW=(size_t)H*Wd;
    const int plane=Bn*H*Wd;
    const float inv_k=1.0f/(float)K;

    const uint32_t aRel=((wm*32+(lane&15))*XS+(lane>>4)*8)*2;
    const uint32_t bRel=(((lane>>4)*8+(lane&7))*XS+((lane>>3)&1)*8)*2;
    const uint32_t aXb[2]={sb+SM_X+aRel, sb+SM_X2+aRel};
    const uint32_t xBase[2]={sb+SM_X, sb+SM_X2};
    const uint32_t aY0=sb+SM_Y0+aRel;
    const uint32_t bW1=sb+SM_W1+bRel+(wn*16)*XS*2;
    const uint32_t bW2=sb+SM_W2+bRel+(wn*16)*XS*2;
    const uint32_t bW3=sb+SM_W3+bRel+(wn*8)*XS*2;
    const uint32_t bWR=sb+SM_WR+bRel+(wn*16)*XS*2;

    const int cta=blockIdx.x;
    const int t0=(int)(((long long)cta*NTILES)/NSM);
    const int t1=(int)(((long long)(cta+1)*NTILES)/NSM);
    int cur_h=-1;

    // ---- initial: prefetch t0 (all threads), wait, stage into buf0 ----
    {
        const int hb=t0/5, wt=t0-hb*5, h=hb>>1, b=hb&1;
        const float* base=x+(size_t)b*64*HW+(size_t)h*Wd;
        #pragma unroll
        for(int i=0;i<4;++i){
            const int chunk=tid+i*TPB, c=chunk>>5, g=chunk&31;
            const int w=min(wt*PXT+g*4, Wd-4);
            cp16(sb+SM_XA+(c*128+g*4)*4, base+(size_t)c*HW+w);
        }
        asm volatile("cp.async.commit_group;" ::: "memory");
        asm volatile("cp.async.wait_group 0;" ::: "memory");
        __syncthreads();
        const int px=tid&127, c0=(tid>>7)*16;
        #pragma unroll
        for(int j=0;j<8;++j){
            const int c=c0+2*j;
            uint32_t s[2];
            split2pair(xa[c*128+px], xa[(c+1)*128+px], s);
            const uint32_t a=xBase[0]+(px*XS+c)*2;
            sts32(a,s[0]); sts32(a+XSPL,s[1]);
        }
        // prefetch t0+1 (GROUP B threads only — they wait it in-loop)
        if(warp>=4 && t0+1<t1){
            const int hb2=(t0+1)/5, wt2=(t0+1)-hb2*5, h2=hb2>>1, b2=hb2&1;
            const float* b2p=x+(size_t)b2*64*HW+(size_t)h2*Wd;
            for(int i=tid-128;i<2048;i+=384){
                const int c=i>>5, g=i&31;
                const int w=min(wt2*PXT+g*4, Wd-4);
                cp16(sb+SM_XA+(c*128+g*4)*4, b2p+(size_t)c*HW+w);
            }
            asm volatile("cp.async.commit_group;" ::: "memory");
        }
        __syncthreads();
    }

    for(int t=t0;t<t1;++t){
        const int hb=t/5, wt=t-hb*5;
        const int h=hb>>1, b=hb&1;
        const int w0=wt*PXT;
        const int pix_base=(b*H+h)*Wd;
        const int p=(t-t0)&1;

        // ---- restage weights on h change (uniform condition) ----
        if(h!=cur_h){
            cur_h=h;
            const float* g1=W1g+h*4096;
            const float* g2=W2g+h*4096;
            #pragma unroll
            for(int i=0;i<4;++i){
                const int pp=tid+i*TPB;
                const int n=pp>>5, c0=(pp&31)*2;
                uint32_t s[2];
                const float2 v1=*reinterpret_cast<const float2*>(g1+n*64+c0);
                split2pair(v1.x,v1.y,s);
                uint32_t a=sb+SM_W1+(n*XS+c0)*2;
                sts32(a,s[0]); sts32(a+WSPL,s[1]);
                const float2 v2=*reinterpret_cast<const float2*>(g2+n*64+c0);
                split2pair(v2.x,v2.y,s);
                a=sb+SM_W2+(n*XS+c0)*2;
                sts32(a,s[0]); sts32(a+WSPL,s[1]);
            }
            const float* g3=W3g+h*2048;
            #pragma unroll
            for(int i=0;i<2;++i){
                const int pp=tid+i*TPB;
                const int n=pp>>5, c0=(pp&31)*2;
                uint32_t s[2];
                const float2 v=*reinterpret_cast<const float2*>(g3+n*64+c0);
                split2pair(v.x,v.y,s);
                const uint32_t a=sb+SM_W3+(n*XS+c0)*2;
                sts32(a,s[0]); sts32(a+W3SPL,s[1]);
            }
            const float* gr=Wr+(size_t)(h*K)*128;
            const int n=tid>>3, k=n>>1, o=n&1;
            #pragma unroll
            for(int j=0;j<4;++j){
                const int c=2*((tid&7)+j*8);
                uint32_t s[2];
                split2pair(gr[k*128+c*2+o], gr[k*128+(c+1)*2+o], s);
                const uint32_t a=sb+SM_WR+(n*XS+c)*2;
                sts32(a,s[0]); sts32(a+WSPL,s[1]);
            }
            if(tid<64){
                smf[SM_B1/4+tid]=b1g[h*64+tid];
                smf[SM_B2/4+tid]=b2g[h*64+tid];
                smf[SM_BR/4+tid]=br[h*64+tid];
            }
            if(tid<32) smf[SM_B3/4+tid]=b3g[h*32+tid];
            __syncthreads();
        }

        if(tid==0) *sNF=0;

        // ---- L1 + Dr fused: reads xbuf[p] ----
        float Dr[4][4];
        {
            float D1[4][4];
            gemm3_dual(aXb[p], bW1, bWR, D1, Dr);
            epi2(D1, smf+SM_B1/4, sb+SM_Y0, wm, wn, lane);
        }
        __syncthreads();

        // ---- L2: Y1 -> xbuf[p] (X(t) dead) ----
        {
            float D2[4][4];
            gemm3(aY0, bW2, D2);
            epi2(D2, smf+SM_B2/4, xBase[p], wm, wn, lane);
        }
        __syncthreads();

        // ---- L3 + Dr spill ----
        {
            float D3[2][4];
            gemm3_n8(aXb[p], bW3, D3);
            const float* b3s=smf+SM_B3/4;
            const int g=lane>>2, c2=2*(lane&3);
            const int n0=wn*8+c2;
            const float bv0=b3s[n0], bv1=b3s[n0+1];
            #pragma unroll
            for(int mt=0;mt<2;++mt){
                #pragma unroll
                for(int half=0;half<2;++half){
                    const float va=D3[mt][half*2]+bv0;
                    const float vb=D3[mt][half*2+1]+bv1;
                    float v1=(vb>va)?vb:va;
                    int   i1=(vb>va)?n0+1:n0;
                    float v2=(vb>va)?va:vb;
                    #pragma unroll
                    for(int m=1;m<=2;m<<=1){
                        const float u1=__shfl_xor_sync(0xFFFFFFFFu,v1,m);
                        const int   j1=__shfl_xor_sync(0xFFFFFFFFu,i1,m);
                        const float u2=__shfl_xor_sync(0xFFFFFFFFu,v2,m);
                        if(u1>v1 || (u1==v1 && j1<i1)){ v2=fmaxf(v1,u2); v1=u1; i1=j1; }
                        else { v2=fmaxf(u1,v2); }
                    }
                    if((lane&3)==0){
                        const int r=wm*32+mt*16+half*8+g;
                        sV1[wn*128+r]=v1; sV2[wn*128+r]=v2; sI1[wn*128+r]=i1;
                    }
                }
            }
            float* dr=reinterpret_cast<float*>(smem+SM_DR);
            #pragma unroll
            for(int mt=0;mt<2;++mt)
                #pragma unroll
                for(int nt=0;nt<2;++nt){
                    const int n2=wn*16+nt*8+c2;
                    const float* d=Dr[mt*2+nt];
                    *reinterpret_cast<float2*>(dr+(wm*32+mt*16+g)*DRS+n2)  =make_float2(d[0],d[1]);
                    *reinterpret_cast<float2*>(dr+(wm*32+mt*16+g+8)*DRS+n2)=make_float2(d[2],d[3]);
                }
        }
        __syncthreads();

        // ==== split phase: Group A (warps 0-3) = tail; Group B (4-15) = stage next X ====
        if(warp<4){
            // ---- tail A ----
            {
                const int px=tid, wc=w0+px;
                if(wc<Wd){
                    float top1=-3.402823466e38f, sec=-3.402823466e38f; int bk=0;
                    #pragma unroll
                    for(int q=0;q<4;++q){
                        const float v1=sV1[q*128+px], v2=sV2[q*128+px];
                        const int   i1=sI1[q*128+px];
                        if(v1>top1){ sec=fmaxf(top1,v2); top1=v1; bk=i1; }
                        else       { sec=fmaxf(sec,v1); }
                    }
                    if(top1-sec < TAU){
                        sFL[atomicAdd(sNF,1)]=px;
                    } else {
                        const float* dr=reinterpret_cast<const float*>(smem+SM_DR);
                        const float2 dv=*reinterpret_cast<const float2*>(dr+px*DRS+2*bk);
                        const float reg0=lrelu(dv.x+smf[SM_BR/4+2*bk]);
                        const float reg1=lrelu(dv.y+smf[SM_BR/4+2*bk+1]);
                        const int flat=h*K+bk;
                        out[pix_base+wc]      =((float)flat+reg0)*inv_k;
                        out[plane+pix_base+wc]=lrelu(reg1);
                    }
                }
            }
            asm volatile("bar.sync 2, 128;" ::: "memory");
            // ---- tail B: exact recompute from split-reconstructed weights ----
            {
                const int nF=*sNF;
                for(int f=warp; f<nF; f+=4){
                    const int px=sFL[f];
                    const int wc=w0+px;
                    float* sw=scr+warp*128;
                    const float* xg=x+(size_t)b*64*HW+(size_t)h*Wd+wc;
                    sw[lane]   =__ldg(xg+(size_t)lane*HW);
                    sw[lane+32]=__ldg(xg+(size_t)(lane+32)*HW);
                    __syncwarp();
                    #pragma unroll
                    for(int r=0;r<2;++r){
                        const int o=lane+r*32;
                        float acc=smf[SM_B1/4+o];
                        const uint32_t wb=sb+SM_W1+(o*XS)*2;
                        #pragma unroll
                        for(int c=0;c<64;c+=2){
                            const float2 w=recon2(lds32(wb+c*2), lds32(wb+c*2+WSPL));
                            acc=fmaf(w.x,sw[c],fmaf(w.y,sw[c+1],acc));
                        }
                        sw[64+o]=lrelu(acc);
                    }
                    __syncwarp();
                    float y1v[2];
                    #pragma unroll
                    for(int r=0;r<2;++r){
                        const int o=lane+r*32;
                        float acc=smf[SM_B2/4+o];
                        const uint32_t wb=sb+SM_W2+(o*XS)*2;
                        #pragma unroll
                        for(int c=0;c<64;c+=2){
                            const float2 w=recon2(lds32(wb+c*2), lds32(wb+c*2+WSPL));
                            acc=fmaf(w.x,sw[64+c],fmaf(w.y,sw[64+c+1],acc));
                        }
                        y1v[r]=lrelu(acc);
                    }
                    __syncwarp();
                    sw[lane]=y1v[0]; sw[lane+32]=y1v[1];
                    __syncwarp();
                    float v; int idx=lane;
                    {
                        float acc=smf[SM_B3/4+lane];
                        const uint32_t wb=sb+SM_W3+(lane*XS)*2;
                        #pragma unroll
                        for(int c=0;c<64;c+=2){
                            const float2 w=recon2(lds32(wb+c*2), lds32(wb+c*2+W3SPL));
                            acc=fmaf(w.x,sw[c],fmaf(w.y,sw[c+1],acc));
                        }
                        v=acc;
                    }
                    #pragma unroll
                    for(int m=16;m>=1;m>>=1){
                        const float ov=__shfl_xor_sync(0xFFFFFFFFu,v,m);
                        const int   oi=__shfl_xor_sync(0xFFFFFFFFu,idx,m);
                        if(ov>v || (ov==v && oi<idx)){ v=ov; idx=oi; }
                    }
                    if(lane==0){
                        const int bk=idx;
                        const float* dr=reinterpret_cast<const float*>(smem+SM_DR);
                        const float2 dv=*reinterpret_cast<const float2*>(dr+px*DRS+2*bk);
                        const float reg0=lrelu(dv.x+smf[SM_BR/4+2*bk]);
                        const float reg1=lrelu(dv.y+smf[SM_BR/4+2*bk+1]);
                        const int flat=h*K+bk;
                        out[pix_base+wc]      =((float)flat+reg0)*inv_k;
                        out[plane+pix_base+wc]=lrelu(reg1);
                    }
                }
            }
        } else {
            // ---- Group B: stage next X splits + issue t+2 prefetch ----
            if(t+1<t1){
                asm volatile("cp.async.wait_group 0;" ::: "memory");
                asm volatile("bar.sync 1, 384;" ::: "memory");   // xa visible group-wide
                const uint32_t xb2=xBase[1-p];
                for(int i=tid-128;i<4096;i+=384){
                    const int px=i&127, c=2*(i>>7);
                    uint32_t s[2];
                    split2pair(xa[c*128+px], xa[(c+1)*128+px], s);
                    const uint32_t a=xb2+(px*XS+c)*2;
                    sts32(a,s[0]); sts32(a+XSPL,s[1]);
                }
                asm volatile("bar.sync 1, 384;" ::: "memory");   // all xa reads done
                if(t+2<t1){
                    const int hb2=(t+2)/5, wt2=(t+2)-hb2*5, h2=hb2>>1, b2=hb2&1;
                    const float* b2p=x+(size_t)b2*64*HW+(size_t)h2*Wd;
                    for(int i=tid-128;i<2048;i+=384){
                        const int c=i>>5, g=i&31;
                        const int w=min(wt2*PXT+g*4, Wd-4);
                        cp16(sb+SM_XA+(c*128+g*4)*4, b2p+(size_t)c*HW+w);
                    }
                    asm volatile("cp.async.commit_group;" ::: "memory");
                }
            }
        }
        __syncthreads();    // join; xbuf[1-p] ready; out/tail done
    }
}

extern "C" void kernel_launch(void* const* d_in, const int* in_sizes, int n_in,
                              void* d_out, int out_size)
{
    const float* x =(const float*)d_in[0];
    const float* W1=(const float*)d_in[1];
    const float* b1=(const float*)d_in[2];
    const float* W2=(const float*)d_in[3];
    const float* b2=(const float*)d_in[4];
    const float* W3=(const float*)d_in[5];
    const float* b3=(const float*)d_in[6];
    const float* Wr=(const float*)d_in[7];
    const float* br=(const float*)d_in[8];
    float* out=(float*)d_out;

    cudaFuncSetAttribute(reg1stage_emu,
                         cudaFuncAttributeMaxDynamicSharedMemorySize, SMEM_BYTES);
    reg1stage_emu<<<NSM,TPB,SMEM_BYTES>>>(x,W1,b1,W2,b2,W3,b3,Wr,br,out);
}

// round 17
// speedup vs baseline: 1.1530x; 1.1530x over previous
#include <cuda_runtime.h>
#include <cuda_bf16.h>
#include <cstdint>

namespace {
constexpr int H=448, Wd=608, K=32, Bn=2, TPB=512, PXT=128;
constexpr int NTILES=H*Bn*5;                // 4480
constexpr int XS=72;                        // bf16 row stride (144B)
constexpr int XSPL=128*XS*2;                // 18432 per activation split
constexpr int WSPL=64*XS*2;                 // 9216
constexpr int W3SPL=32*XS*2;                // 4608
constexpr float TAU=2e-4f;

constexpr int SM_B1=0, SM_B2=256, SM_B3=512, SM_BR=640;
constexpr int SM_PV1=1024;                  // [4][128] f32 top1
constexpr int SM_PV2=3072;                  // [4][128] f32 top2
constexpr int SM_PI1=5120;                  // [4][128] i32 idx
constexpr int SM_SCR=7808;                  // 16 warps x 128 f32 (8192)
constexpr int SM_XA=16000;                  // raw x prefetch [64][128] f32 (32768)
constexpr int SM_X =48768;                  // X splits (Y1 overlays)
constexpr int SM_Y0=SM_X+2*XSPL;            // 85632 (Dr f32 overlay)
constexpr int SM_W1=SM_Y0+2*XSPL;           // 122496
constexpr int SM_W2=SM_W1+2*WSPL;           // 140928
constexpr int SM_W3=SM_W2+2*WSPL;           // 159360
constexpr int SM_WR=SM_W3+2*W3SPL;          // 168576
constexpr int SM_WF1=SM_WR+2*WSPL;          // 187008  fp32 W1 [64][65]
constexpr int SM_WF2=SM_WF1+64*65*4;        // 203648  fp32 W2 [64][65]
constexpr int SM_WF3=SM_WF2+64*65*4;        // 220288  fp32 W3 [32][65]
constexpr int SMEM_BYTES=SM_WF3+32*65*4;    // 228608
constexpr int SM_DR=SM_Y0;
constexpr int DRS=66;
}

__device__ __forceinline__ float lrelu(float v){ return v>=0.f ? v : 0.01f*v; }
__device__ __forceinline__ uint32_t smem_u32(const void* p){
    uint32_t a;
    asm("{ .reg .u64 t; cvta.to.shared.u64 t, %1; cvt.u32.u64 %0, t; }" : "=r"(a) : "l"(p));
    return a;
}
__device__ __forceinline__ void sts32(uint32_t a, uint32_t v){
    asm volatile("st.shared.b32 [%0], %1;" :: "r"(a), "r"(v) : "memory");
}
__device__ __forceinline__ void cp16(uint32_t dst, const void* src){
    asm volatile("cp.async.cg.shared.global [%0], [%1], 16;" :: "r"(dst), "l"(src) : "memory");
}
__device__ __forceinline__ void ldsm4(uint32_t addr, uint32_t* r){
    asm volatile("ldmatrix.sync.aligned.m8n8.x4.shared.b16 {%0,%1,%2,%3}, [%4];"
                 : "=r"(r[0]), "=r"(r[1]), "=r"(r[2]), "=r"(r[3]) : "r"(addr));
}
__device__ __forceinline__ void ldsm2(uint32_t addr, uint32_t* r){
    asm volatile("ldmatrix.sync.aligned.m8n8.x2.shared.b16 {%0,%1}, [%2];"
                 : "=r"(r[0]), "=r"(r[1]) : "r"(addr));
}
__device__ __forceinline__ void mma_bf16(float d[4], const uint32_t a[4], uint32_t b0, uint32_t b1){
    asm volatile("mma.sync.aligned.m16n8k16.row.col.f32.bf16.bf16.f32 "
                 "{%0,%1,%2,%3},{%4,%5,%6,%7},{%8,%9},{%0,%1,%2,%3};"
                 : "+f"(d[0]), "+f"(d[1]), "+f"(d[2]), "+f"(d[3])
                 : "r"(a[0]), "r"(a[1]), "r"(a[2]), "r"(a[3]), "r"(b0), "r"(b1));
}
__device__ __forceinline__ uint32_t prmt_(uint32_t a, uint32_t b, uint32_t s){
    uint32_t d; asm("prmt.b32 %0,%1,%2,%3;" : "=r"(d) : "r"(a), "r"(b), "r"(s)); return d;
}
__device__ __forceinline__ void split2pair(float a, float b, uint32_t s[2]){
    const uint32_t ia=__float_as_uint(a)+0x8000u, ib=__float_as_uint(b)+0x8000u;
    s[0]=prmt_(ia, ib, 0x7632u);
    const float ra=a-__uint_as_float(ia&0xFFFF0000u);
    const float rb=b-__uint_as_float(ib&0xFFFF0000u);
    uint32_t r; asm("cvt.rn.bf16x2.f32 %0, %1, %2;" : "=r"(r) : "f"(rb), "f"(ra));
    s[1]=r;
}

// ---- 2-split 3-pass emulated GEMMs; warp tile 32px x 16n ----
__device__ __forceinline__ void gemm3(uint32_t aB, uint32_t bB, float D[4][4]){
    uint32_t bf[4][2][4];
    #pragma unroll
    for(int ks=0;ks<4;++ks)
        #pragma unroll
        for(int s=0;s<2;++s) ldsm4(bB+s*WSPL+ks*32, bf[ks][s]);
    #pragma unroll
    for(int i=0;i<4;++i){ D[i][0]=D[i][1]=D[i][2]=D[i][3]=0.f; }
    constexpr int PA[3]={0,0,1}, PB[3]={0,1,0};
    #pragma unroll
    for(int ks=0;ks<4;++ks){
        uint32_t a[2][2][4];
        #pragma unroll
        for(int s=0;s<2;++s){
            ldsm4(aB+s*XSPL+ks*32, a[s][0]);
            ldsm4(aB+s*XSPL+16*XS*2+ks*32, a[s][1]);
        }
        #pragma unroll
        for(int p=0;p<3;++p)
            #pragma unroll
            for(int mt=0;mt<2;++mt)
                #pragma unroll
                for(int nt=0;nt<2;++nt)
                    mma_bf16(D[mt*2+nt], a[PA[p]][mt],
                             bf[ks][PB[p]][nt*2], bf[ks][PB[p]][nt*2+1]);
    }
}
__device__ __forceinline__ void gemm3_dual(uint32_t aB, uint32_t b1B, uint32_t b2B,
                                           float D1[4][4], float D2[4][4]){
    #pragma unroll
    for(int i=0;i<4;++i){ D1[i][0]=D1[i][1]=D1[i][2]=D1[i][3]=0.f;
                          D2[i][0]=D2[i][1]=D2[i][2]=D2[i][3]=0.f; }
    constexpr int PA[3]={0,0,1}, PB[3]={0,1,0};
    #pragma unroll
    for(int ks=0;ks<4;++ks){
        uint32_t a[2][2][4];
        #pragma unroll
        for(int s=0;s<2;++s){
            ldsm4(aB+s*XSPL+ks*32, a[s][0]);
            ldsm4(aB+s*XSPL+16*XS*2+ks*32, a[s][1]);
        }
        uint32_t bf1[2][4], bf2[2][4];
        #pragma unroll
        for(int s=0;s<2;++s){
            ldsm4(b1B+s*WSPL+ks*32, bf1[s]);
            ldsm4(b2B+s*WSPL+ks*32, bf2[s]);
        }
        #pragma unroll
        for(int p=0;p<3;++p)
            #pragma unroll
            for(int mt=0;mt<2;++mt)
                #pragma unroll
                for(int nt=0;nt<2;++nt){
                    mma_bf16(D1[mt*2+nt], a[PA[p]][mt], bf1[PB[p]][nt*2], bf1[PB[p]][nt*2+1]);
                    mma_bf16(D2[mt*2+nt], a[PA[p]][mt], bf2[PB[p]][nt*2], bf2[PB[p]][nt*2+1]);
                }
    }
}
__device__ __forceinline__ void gemm3_n8(uint32_t aB, uint32_t bB, float D[2][4]){
    uint32_t bf[4][2][2];
    #pragma unroll
    for(int ks=0;ks<4;++ks)
        #pragma unroll
        for(int s=0;s<2;++s) ldsm2(bB+s*W3SPL+ks*32, bf[ks][s]);
    #pragma unroll
    for(int i=0;i<2;++i){ D[i][0]=D[i][1]=D[i][2]=D[i][3]=0.f; }
    constexpr int PA[3]={0,0,1}, PB[3]={0,1,0};
    #pragma unroll
    for(int ks=0;ks<4;++ks){
        uint32_t a[2][2][4];
        #pragma unroll
        for(int s=0;s<2;++s){
            ldsm4(aB+s*XSPL+ks*32, a[s][0]);
            ldsm4(aB+s*XSPL+16*XS*2+ks*32, a[s][1]);
        }
        #pragma unroll
        for(int p=0;p<3;++p)
            #pragma unroll
            for(int mt=0;mt<2;++mt)
                mma_bf16(D[mt], a[PA[p]][mt], bf[ks][PB[p]][0], bf[ks][PB[p]][1]);
    }
}

// bias + lrelu + 2-split bf16 store; warp covers 32px (rowb..rowb+31) x 16n
__device__ __forceinline__ void epi2(float D[4][4], const float* __restrict__ bias,
                                     uint32_t outB, int rowb, int wn, int lane){
    const int g=lane>>2, c2=2*(lane&3);
    #pragma unroll
    for(int mt=0;mt<2;++mt)
        #pragma unroll
        for(int nt=0;nt<2;++nt){
            const int n0=wn*16+nt*8+c2;
            const float bv0=bias[n0], bv1=bias[n0+1];
            const float* d=D[mt*2+nt];
            uint32_t s[2];
            const uint32_t a0=outB+((rowb+mt*16+g)*XS+n0)*2;
            split2pair(lrelu(d[0]+bv0), lrelu(d[1]+bv1), s);
            sts32(a0,s[0]); sts32(a0+XSPL,s[1]);
            const uint32_t a1=a0+8*XS*2;
            split2pair(lrelu(d[2]+bv0), lrelu(d[3]+bv1), s);
            sts32(a1,s[0]); sts32(a1+XSPL,s[1]);
        }
}

__global__ void __launch_bounds__(TPB,1)
reg1stage_emu(const float* __restrict__ x,
              const float* __restrict__ W1g, const float* __restrict__ b1g,
              const float* __restrict__ W2g, const float* __restrict__ b2g,
              const float* __restrict__ W3g, const float* __restrict__ b3g,
              const float* __restrict__ Wr,  const float* __restrict__ br,
              float* __restrict__ out)
{
    extern __shared__ char smem[];
    const uint32_t sb = smem_u32(smem);
    float* smf = reinterpret_cast<float*>(smem);
    float* sV1 = reinterpret_cast<float*>(smem+SM_PV1);
    float* sV2 = reinterpret_cast<float*>(smem+SM_PV2);
    int*   sI1 = reinterpret_cast<int*>(smem+SM_PI1);
    float* scr = reinterpret_cast<float*>(smem+SM_SCR);
    float* xa  = reinterpret_cast<float*>(smem+SM_XA);
    float* w1f = reinterpret_cast<float*>(smem+SM_WF1);
    float* w2f = reinterpret_cast<float*>(smem+SM_WF2);
    float* w3f = reinterpret_cast<float*>(smem+SM_WF3);
    const int tid=threadIdx.x, lane=tid&31, warp=tid>>5;
    const int half=warp>>3;                 // 0/1: px [0,64) / [64,128)
    const int wmh=(warp&7)>>2;              // m-group within half
    const int wn=warp&3;                    // n-group
    const int rowb=half*64+wmh*32;
    const uint32_t barid=half+1;

    const size_t HW=(size_t)H*Wd;
    const int plane=Bn*H*Wd;
    const float inv_k=1.0f/(float)K;

    const uint32_t aRel=((rowb+(lane&15))*XS+(lane>>4)*8)*2;
    const uint32_t bRel=(((lane>>4)*8+(lane&7))*XS+((lane>>3)&1)*8)*2;
    const uint32_t aX =sb+SM_X +aRel;
    const uint32_t aY0=sb+SM_Y0+aRel;
    const uint32_t bW1=sb+SM_W1+bRel+(wn*16)*XS*2;
    const uint32_t bW2=sb+SM_W2+bRel+(wn*16)*XS*2;
    const uint32_t bW3=sb+SM_W3+bRel+(wn*8)*XS*2;
    const uint32_t bWR=sb+SM_WR+bRel+(wn*16)*XS*2;

    const int nsm=gridDim.x;
    const int cta=blockIdx.x;
    const int t0=(int)(((long long)cta*NTILES)/nsm);
    const int t1=(int)(((long long)(cta+1)*NTILES)/nsm);
    int cur_h=-1;

    // initial prefetch for t0
    {
        const int hb=t0/5, wt=t0-hb*5, h=hb>>1, b=hb&1;
        const float* base=x+(size_t)b*64*HW+(size_t)h*Wd;
        #pragma unroll
        for(int i=0;i<4;++i){
            const int chunk=tid+i*TPB, c=chunk>>5, g=chunk&31;
            const int w=min(wt*PXT+g*4, Wd-4);
            cp16(sb+SM_XA+(c*128+g*4)*4, base+(size_t)c*HW+w);
        }
        asm volatile("cp.async.commit_group;" ::: "memory");
    }

    for(int t=t0;t<t1;++t){
        const int hb=t/5, wt=t-hb*5;
        const int h=hb>>1, b=hb&1;
        const int w0=wt*PXT;
        const int pix_base=(b*H+h)*Wd;

        asm volatile("cp.async.wait_group 0;" ::: "memory");
        __syncthreads();            // xa arrived; prev tile fully done

        // ---- restage weights on h change ----
        if(h!=cur_h){
            cur_h=h;
            const float* g1=W1g+h*4096;
            const float* g2=W2g+h*4096;
            #pragma unroll
            for(int i=0;i<4;++i){
                const int p=tid+i*TPB;
                const int n=p>>5, c0=(p&31)*2;
                uint32_t s[2];
                const float2 v1=*reinterpret_cast<const float2*>(g1+n*64+c0);
                split2pair(v1.x,v1.y,s);
                uint32_t a=sb+SM_W1+(n*XS+c0)*2;
                sts32(a,s[0]); sts32(a+WSPL,s[1]);
                w1f[n*65+c0]=v1.x; w1f[n*65+c0+1]=v1.y;
                const float2 v2=*reinterpret_cast<const float2*>(g2+n*64+c0);
                split2pair(v2.x,v2.y,s);
                a=sb+SM_W2+(n*XS+c0)*2;
                sts32(a,s[0]); sts32(a+WSPL,s[1]);
                w2f[n*65+c0]=v2.x; w2f[n*65+c0+1]=v2.y;
            }
            const float* g3=W3g+h*2048;
            #pragma unroll
            for(int i=0;i<2;++i){
                const int p=tid+i*TPB;
                const int n=p>>5, c0=(p&31)*2;
                uint32_t s[2];
                const float2 v=*reinterpret_cast<const float2*>(g3+n*64+c0);
                split2pair(v.x,v.y,s);
                const uint32_t a=sb+SM_W3+(n*XS+c0)*2;
                sts32(a,s[0]); sts32(a+W3SPL,s[1]);
                w3f[n*65+c0]=v.x; w3f[n*65+c0+1]=v.y;
            }
            const float* gr=Wr+(size_t)(h*K)*128;
            const int n=tid>>3, k=n>>1, o=n&1;
            #pragma unroll
            for(int j=0;j<4;++j){
                const int c=2*((tid&7)+j*8);
                uint32_t s[2];
                split2pair(gr[k*128+c*2+o], gr[k*128+(c+1)*2+o], s);
                const uint32_t a=sb+SM_WR+(n*XS+c)*2;
                sts32(a,s[0]); sts32(a+WSPL,s[1]);
            }
            if(tid<64){
                smf[SM_B1/4+tid]=b1g[h*64+tid];
                smf[SM_B2/4+tid]=b2g[h*64+tid];
                smf[SM_BR/4+tid]=br[h*64+tid];
            }
            if(tid<32) smf[SM_B3/4+tid]=b3g[h*32+tid];
        }

        // ---- stage X from xa: LDS -> 2 bf16 splits ----
        {
            const int px=tid&127, c0=(tid>>7)*16;
            #pragma unroll
            for(int j=0;j<8;++j){
                const int c=c0+2*j;
                uint32_t s[2];
                split2pair(xa[c*128+px], xa[(c+1)*128+px], s);
                const uint32_t a=sb+SM_X+(px*XS+c)*2;
                sts32(a,s[0]); sts32(a+XSPL,s[1]);
            }
        }
        __syncthreads();            // weights + X splits visible; xa consumed

        // ---- prefetch next tile's x (overlaps compute) ----
        if(t+1<t1){
            const int hb2=(t+1)/5, wt2=(t+1)-hb2*5, h2=hb2>>1, b2=hb2&1;
            const float* base=x+(size_t)b2*64*HW+(size_t)h2*Wd;
            #pragma unroll
            for(int i=0;i<4;++i){
                const int chunk=tid+i*TPB, c=chunk>>5, g=chunk&31;
                const int w=min(wt2*PXT+g*4, Wd-4);
                cp16(sb+SM_XA+(c*128+g*4)*4, base+(size_t)c*HW+w);
            }
            asm volatile("cp.async.commit_group;" ::: "memory");
        }

        // ==== per-half pipeline (named barriers) ====
        // ---- L1 + Dr fused ----
        float Dr[4][4];
        {
            float D1[4][4];
            gemm3_dual(aX, bW1, bWR, D1, Dr);
            epi2(D1, smf+SM_B1/4, sb+SM_Y0, rowb, wn, lane);
        }
        asm volatile("bar.sync %0, 256;" :: "r"(barid) : "memory");

        // ---- L2: Y1 -> X buffer (X rows of this half dead) ----
        {
            float D2[4][4];
            gemm3(aY0, bW2, D2);
            epi2(D2, smf+SM_B2/4, sb+SM_X, rowb, wn, lane);
        }
        asm volatile("bar.sync %0, 256;" :: "r"(barid) : "memory");

        // ---- L3 + top-2 partials + Dr spill ----
        {
            float D3[2][4];
            gemm3_n8(aX, bW3, D3);
            const float* b3s=smf+SM_B3/4;
            const int g=lane>>2, c2=2*(lane&3);
            const int n0=wn*8+c2;
            const float bv0=b3s[n0], bv1=b3s[n0+1];
            #pragma unroll
            for(int mt=0;mt<2;++mt){
                #pragma unroll
                for(int dh=0;dh<2;++dh){
                    const float va=D3[mt][dh*2]+bv0;
                    const float vb=D3[mt][dh*2+1]+bv1;
                    float v1=(vb>va)?vb:va;
                    int   i1=(vb>va)?n0+1:n0;
                    float v2=(vb>va)?va:vb;
                    #pragma unroll
                    for(int m=1;m<=2;m<<=1){
                        const float u1=__shfl_xor_sync(0xFFFFFFFFu,v1,m);
                        const int   j1=__shfl_xor_sync(0xFFFFFFFFu,i1,m);
                        const float u2=__shfl_xor_sync(0xFFFFFFFFu,v2,m);
                        if(u1>v1 || (u1==v1 && j1<i1)){ v2=fmaxf(v1,u2); v1=u1; i1=j1; }
                        else { v2=fmaxf(u1,v2); }
                    }
                    if((lane&3)==0){
                        const int r=rowb+mt*16+dh*8+g;
                        sV1[wn*128+r]=v1; sV2[wn*128+r]=v2; sI1[wn*128+r]=i1;
                    }
                }
            }
            float* dr=reinterpret_cast<float*>(smem+SM_DR);
            #pragma unroll
            for(int mt=0;mt<2;++mt)
                #pragma unroll
                for(int nt=0;nt<2;++nt){
                    const int n2=wn*16+nt*8+c2;
                    const float* d=Dr[mt*2+nt];
                    *reinterpret_cast<float2*>(dr+(rowb+mt*16+g)*DRS+n2)  =make_float2(d[0],d[1]);
                    *reinterpret_cast<float2*>(dr+(rowb+mt*16+g+8)*DRS+n2)=make_float2(d[2],d[3]);
                }
        }
        asm volatile("bar.sync %0, 256;" :: "r"(barid) : "memory");

        // ---- fused tail: each warp owns 8 pixels ----
        {
            const int pxb=half*64+(warp&7)*8;
            bool flag=false;
            if(lane<8){
                const int px=pxb+lane, wc=w0+px;
                if(wc<Wd){
                    float top1=-3.402823466e38f, sec=-3.402823466e38f; int bk=0;
                    #pragma unroll
                    for(int q=0;q<4;++q){
                        const float v1=sV1[q*128+px], v2=sV2[q*128+px];
                        const int   i1=sI1[q*128+px];
                        if(v1>top1){ sec=fmaxf(top1,v2); top1=v1; bk=i1; }
                        else       { sec=fmaxf(sec,v1); }
                    }
                    if(top1-sec < TAU){
                        flag=true;
                    } else {
                        const float* dr=reinterpret_cast<const float*>(smem+SM_DR);
                        const float2 dv=*reinterpret_cast<const float2*>(dr+px*DRS+2*bk);
                        const float reg0=lrelu(dv.x+smf[SM_BR/4+2*bk]);
                        const float reg1=lrelu(dv.y+smf[SM_BR/4+2*bk+1]);
                        const int flat=h*K+bk;
                        out[pix_base+wc]      =((float)flat+reg0)*inv_k;
                        out[plane+pix_base+wc]=lrelu(reg1);
                    }
                }
            }
            uint32_t fm=__ballot_sync(0xFFFFFFFFu, flag);
            while(fm){
                const int bit=__ffs(fm)-1; fm&=fm-1;
                const int px=pxb+bit, wc=w0+px;
                float* sw=scr+warp*128;
                const float* xg=x+(size_t)b*64*HW+(size_t)h*Wd+wc;
                sw[lane]   =__ldg(xg+(size_t)lane*HW);
                sw[lane+32]=__ldg(xg+(size_t)(lane+32)*HW);
                __syncwarp();
                #pragma unroll
                for(int r=0;r<2;++r){
                    const int o=lane+r*32;
                    float acc=smf[SM_B1/4+o];
                    const float* wr=w1f+o*65;
                    #pragma unroll
                    for(int c=0;c<64;++c) acc=fmaf(wr[c],sw[c],acc);
                    sw[64+o]=lrelu(acc);     // writes [64..128); reads [0..64) ✓
                }
                __syncwarp();
                float y1v[2];
                #pragma unroll
                for(int r=0;r<2;++r){
                    const int o=lane+r*32;
                    float acc=smf[SM_B2/4+o];
                    const float* wr=w2f+o*65;
                    #pragma unroll
                    for(int c=0;c<64;++c) acc=fmaf(wr[c],sw[64+c],acc);
                    y1v[r]=lrelu(acc);
                }
                __syncwarp();
                sw[lane]=y1v[0]; sw[lane+32]=y1v[1];
                __syncwarp();
                float v; int idx=lane;
                {
                    float acc=smf[SM_B3/4+lane];
                    const float* wr=w3f+lane*65;
                    #pragma unroll
                    for(int c=0;c<64;++c) acc=fmaf(wr[c],sw[c],acc);
                    v=acc;
                }
                #pragma unroll
                for(int m=16;m>=1;m>>=1){
                    const float ov=__shfl_xor_sync(0xFFFFFFFFu,v,m);
                    const int   oi=__shfl_xor_sync(0xFFFFFFFFu,idx,m);
                    if(ov>v || (ov==v && oi<idx)){ v=ov; idx=oi; }
                }
                if(lane==0){
                    const int bk=idx;
                    const float* dr=reinterpret_cast<const float*>(smem+SM_DR);
                    const float2 dv=*reinterpret_cast<const float2*>(dr+px*DRS+2*bk);
                    const float reg0=lrelu(dv.x+smf[SM_BR/4+2*bk]);
                    const float reg1=lrelu(dv.y+smf[SM_BR/4+2*bk+1]);
                    const int flat=h*K+bk;
                    out[pix_base+wc]      =((float)flat+reg0)*inv_k;
                    out[plane+pix_base+wc]=lrelu(reg1);
                }
            }
        }
        // loop-top __syncthreads joins halves before next tile's staging
    }
}

extern "C" void kernel_launch(void* const* d_in, const int* in_sizes, int n_in,
                              void* d_out, int out_size)
{
    const float* x =(const float*)d_in[0];
    const float* W1=(const float*)d_in[1];
    const float* b1=(const float*)d_in[2];
    const float* W2=(const float*)d_in[3];
    const float* b2=(const float*)d_in[4];
    const float* W3=(const float*)d_in[5];
    const float* b3=(const float*)d_in[6];
    const float* Wr=(const float*)d_in[7];
    const float* br=(const float*)d_in[8];
    float* out=(float*)d_out;

    int dev=0; cudaGetDevice(&dev);
    int nsm=0; cudaDeviceGetAttribute(&nsm, cudaDevAttrMultiProcessorCount, dev);
    if(nsm<=0) nsm=148;

    cudaFuncSetAttribute(reg1stage_emu,
                         cudaFuncAttributeMaxDynamicSharedMemorySize, SMEM_BYTES);
    reg1stage_emu<<<nsm,TPB,SMEM_BYTES>>>(x,W1,b1,W2,b2,W3,b3,Wr,br,out);
}